// round 16
// baseline (speedup 1.0000x reference)
#include <cuda_runtime.h>
#include <cuda_fp16.h>
#include <cstdint>

#define HH 56
#define WW 56
#define HWP 3136
#define CGC 16
#define NGRP 1024
#define NT 512
#define EPSV 1e-5f

// byte offsets into dynamic smem
#define OB_SX    0        // fp16 tile 16*3136
#define OB_XH    100352
#define OB_XW    102144
#define OB_RS    103936   // fp16, layout [h*16+c]
#define OB_CS    105728   // fp16, layout [x*16+c]
#define OB_W1    107520   // fp16 256 (half2 pair layout)
#define OB_WC    108544   // half2-dup conv taps + a2c, 16*12 uints
#define OB_SA    109312   // fp32 144
#define OB_B1    109888
#define OB_B3    109952
#define OB_GNW   110016
#define OB_GNB   110080
#define OB_MU    110144
#define OB_SS    110208
#define OB_M2    110272
#define OB_A1    110336
#define OB_A2C   110400
#define OB_CONST 110464
#define OB_ZR    110528   // 128B zero row
#define SMEM_BYTES 110656

__device__ __forceinline__ float wred(float v) {
#pragma unroll
    for (int o = 16; o; o >>= 1) v += __shfl_down_sync(0xffffffffu, v, o);
    return v;
}
__device__ __forceinline__ float sigm(float z) {
    return __fdividef(1.f, 1.f + __expf(-z));
}

__device__ __forceinline__ float4 h4tof4(uint2 u) {
    __half2 a = *reinterpret_cast<__half2*>(&u.x);
    __half2 b = *reinterpret_cast<__half2*>(&u.y);
    float2 fa = __half22float2(a), fb = __half22float2(b);
    return make_float4(fa.x, fa.y, fb.x, fb.y);
}
__device__ __forceinline__ unsigned int hfma2u(unsigned int a, unsigned int b, unsigned int c) {
    __half2 r = __hfma2(*reinterpret_cast<__half2*>(&a),
                        *reinterpret_cast<__half2*>(&b),
                        *reinterpret_cast<__half2*>(&c));
    return *reinterpret_cast<unsigned int*>(&r);
}
__device__ __forceinline__ unsigned int hmul2u(unsigned int a, unsigned int b) {
    __half2 r = __hmul2(*reinterpret_cast<__half2*>(&a),
                        *reinterpret_cast<__half2*>(&b));
    return *reinterpret_cast<unsigned int*>(&r);
}
__device__ __forceinline__ float2 u2f2(unsigned int a) {
    return __half22float2(*reinterpret_cast<__half2*>(&a));
}
__device__ __forceinline__ unsigned int f2h2u(float v) {
    __half2 h = __float2half2_rn(v);
    return *reinterpret_cast<unsigned int*>(&h);
}

// load one conv row (8px + halo) as raw half2 pairs; shifted pairs via PRMT
#define GETROW8(rowptr) do { \
    u = *(const uint4*)((rowptr) + xq8 * 8); \
    unsigned int _pu = __shfl_up_sync(0xffffffffu, u.w, 1, 8); \
    unsigned int _nu = __shfl_down_sync(0xffffffffu, u.x, 1, 8); \
    if (l8 == 0) _pu = 0u; \
    if (l8 == 6) _nu = 0u; \
    p0 = __byte_perm(_pu, u.x, 0x5432); \
    p2 = __byte_perm(u.x, u.y, 0x5432); \
    p4 = __byte_perm(u.y, u.z, 0x5432); \
    p6 = __byte_perm(u.z, u.w, 0x5432); \
    p8 = __byte_perm(u.w, _nu, 0x5432); \
} while (0)

#define HTAPS8(ha, hb, hc, hd, t0, t1, t2) do { \
    ha = hfma2u(t0, p0, hfma2u(t1, u.x, hfma2u(t2, p2, ha))); \
    hb = hfma2u(t0, p2, hfma2u(t1, u.y, hfma2u(t2, p4, hb))); \
    hc = hfma2u(t0, p4, hfma2u(t1, u.z, hfma2u(t2, p6, hc))); \
    hd = hfma2u(t0, p6, hfma2u(t1, u.w, hfma2u(t2, p8, hd))); \
} while (0)

// center tap gets attention folded: tap = w47.x + cfh*wv_j
#define HTAPSV8(ha, hb, hc, hd, t0, cfh, t2) do { \
    ha = hfma2u(t0, p0, hfma2u(hfma2u(cfh, wv.x, w47.x), u.x, hfma2u(t2, p2, ha))); \
    hb = hfma2u(t0, p2, hfma2u(hfma2u(cfh, wv.y, w47.x), u.y, hfma2u(t2, p4, hb))); \
    hc = hfma2u(t0, p4, hfma2u(hfma2u(cfh, wv.z, w47.x), u.z, hfma2u(t2, p6, hc))); \
    hd = hfma2u(t0, p6, hfma2u(hfma2u(cfh, wv.w, w47.x), u.w, hfma2u(t2, p8, hd))); \
} while (0)

__global__ __launch_bounds__(NT, 2)
void ema_fused_kernel(const float* __restrict__ x,
                      const float* __restrict__ w1, const float* __restrict__ b1,
                      const float* __restrict__ w3, const float* __restrict__ b3,
                      const float* __restrict__ gnw, const float* __restrict__ gnb,
                      float* __restrict__ out) {
    extern __shared__ char smc[];
    __half* SXH = (__half*)(smc + OB_SX);
    __half* XHh = (__half*)(smc + OB_XH);
    __half* XWh = (__half*)(smc + OB_XW);
    __half* RSh = (__half*)(smc + OB_RS);
    __half* CSh = (__half*)(smc + OB_CS);
    __half* W1h = (__half*)(smc + OB_W1);
    unsigned int* WCu = (unsigned int*)(smc + OB_WC);
    float* SA  = (float*)(smc + OB_SA);
    float* B1s = (float*)(smc + OB_B1);
    float* B3s = (float*)(smc + OB_B3);
    float* GNWs = (float*)(smc + OB_GNW);
    float* GNBs = (float*)(smc + OB_GNB);
    float* MU  = (float*)(smc + OB_MU);
    float* SSv = (float*)(smc + OB_SS);
    float* M2  = (float*)(smc + OB_M2);
    float* A1v = (float*)(smc + OB_A1);
    float* CONSTS = (float*)(smc + OB_CONST);
    __half* ZR = (__half*)(smc + OB_ZR);

    const int tid = threadIdx.x;
    const int g = blockIdx.x;
    const float* gx = x + (size_t)g * (CGC * HWP);
    float* og = out + (size_t)g * (CGC * HWP);

    const int warp = tid >> 5;
    const int lane = tid & 31;

    // ---- Phase 0: streaming load tile (fp32 -> fp16, 8 px chunks) + params + zero row ----
    {
        const float4* gx4 = (const float4*)gx;
#pragma unroll 2
        for (int i = tid; i < (CGC * HWP) / 8; i += NT) {
            float4 v0 = __ldcs(gx4 + 2 * i);
            float4 v1 = __ldcs(gx4 + 2 * i + 1);
            __half2 h0 = __floats2half2_rn(v0.x, v0.y);
            __half2 h1 = __floats2half2_rn(v0.z, v0.w);
            __half2 h2 = __floats2half2_rn(v1.x, v1.y);
            __half2 h3 = __floats2half2_rn(v1.z, v1.w);
            uint4 u;
            u.x = *(unsigned int*)&h0; u.y = *(unsigned int*)&h1;
            u.z = *(unsigned int*)&h2; u.w = *(unsigned int*)&h3;
            *(uint4*)(SXH + i * 8) = u;
        }
        if (tid < 256) W1h[tid] = __float2half_rn(w1[tid]);
        if (tid < 16) {
            B1s[tid] = b1[tid]; B3s[tid] = b3[tid];
            GNWs[tid] = gnw[tid]; GNBs[tid] = gnb[tid];
        }
        if (tid >= 256 && tid < 288) ((float*)ZR)[tid - 256] = 0.f;
    }
    __syncthreads();

    // ---- Phase 1 (rebalanced): cols on 224 threads (4-px segs), rows on 256 threads ----
    // RS/CS stored transposed: RSh[h*16+c], CSh[x*16+c]
    if (tid < 224) {
        int c = tid / 14, seg = tid - c * 14;
        const __half* base = SXH + c * HWP + seg * 4;
        float4 sa = make_float4(0.f, 0.f, 0.f, 0.f);
#pragma unroll 8
        for (int y = 0; y < HH; y++) {
            float4 a = h4tof4(*(const uint2*)(base + y * WW));
            sa.x += a.x; sa.y += a.y; sa.z += a.z; sa.w += a.w;
        }
        CSh[(seg * 4 + 0) * 16 + c] = __float2half_rn(sa.x);
        CSh[(seg * 4 + 1) * 16 + c] = __float2half_rn(sa.y);
        CSh[(seg * 4 + 2) * 16 + c] = __float2half_rn(sa.z);
        CSh[(seg * 4 + 3) * 16 + c] = __float2half_rn(sa.w);
    } else if (tid < 480) {
        for (int r = tid - 224; r < CGC * HH; r += 256) {
            int c = r / HH, h = r - c * HH;
            const uint4* row = (const uint4*)(SXH + r * WW);
            float s = 0.f;
#pragma unroll
            for (int j = 0; j < 7; j++) {
                uint4 u = row[j];
                float4 a = h4tof4(make_uint2(u.x, u.y));
                float4 b = h4tof4(make_uint2(u.z, u.w));
                s += (a.x + a.y) + (a.z + a.w) + (b.x + b.y) + (b.z + b.w);
            }
            RSh[h * 16 + c] = __float2half_rn(s);
        }
    } else if (tid < 496) {
        // a1 = softmax(gn_b) (params only)
        int t = tid - 480;
        float gb = GNBs[t];
        float mx = gb;
#pragma unroll
        for (int o = 8; o; o >>= 1) mx = fmaxf(mx, __shfl_xor_sync(0xffffu, mx, o, 16));
        float e = expf(gb - mx);
        float ssum = e;
#pragma unroll
        for (int o = 8; o; o >>= 1) ssum += __shfl_xor_sync(0xffffu, ssum, o, 16);
        float a = e / ssum;
        A1v[t] = a;
        float cA = a * B3s[t];
#pragma unroll
        for (int o = 8; o; o >>= 1) cA += __shfl_xor_sync(0xffffu, cA, o, 16);
        if (t == 0) CONSTS[0] = cA;
    }
    __syncthreads();

    // ==== Merged Phase 2 (HFMA2 conv1x1+sigmoid) + SA + Phase 3 (stats), warp-per-channel ====
    {
        const int c = warp;
        const float inv56 = 1.f / 56.f;
        const uint4* w1p = (const uint4*)(W1h + c * CGC);
        uint4 wra = w1p[0], wrb = w1p[1];
        for (int ii = lane; ii < HH + WW; ii += 32) {
            const __half* base = (ii < HH) ? (RSh + ii * 16) : (CSh + (ii - HH) * 16);
            uint4 ua = *(const uint4*)base;
            uint4 ub = *(const uint4*)(base + 8);
            unsigned int h = 0u;
            h = hfma2u(wra.x, ua.x, h);
            h = hfma2u(wra.y, ua.y, h);
            h = hfma2u(wra.z, ua.z, h);
            h = hfma2u(wra.w, ua.w, h);
            h = hfma2u(wrb.x, ub.x, h);
            h = hfma2u(wrb.y, ub.y, h);
            h = hfma2u(wrb.z, ub.z, h);
            h = hfma2u(wrb.w, ub.w, h);
            float2 f = u2f2(h);
            float sg = sigm(B1s[c] + (f.x + f.y) * inv56);
            if (ii < HH) XHh[c * HH + ii] = __float2half_rn(sg);
            else         XWh[c * WW + (ii - HH)] = __float2half_rn(sg);
        }
        __syncwarp();

        // channel total + shifted sums SA (lanes 0-8), all channel-local
        float v = __half2float(RSh[lane * 16 + c]) +
                  ((lane < 24) ? __half2float(RSh[(lane + 32) * 16 + c]) : 0.f);
        v = wred(v);
        float vtot = __shfl_sync(0xffffffffu, v, 0);
        if (lane < 9) {
            int oy = lane / 3 - 1, ox = lane % 3 - 1;
            float S = vtot;
            if (oy) S -= __half2float(RSh[(oy < 0 ? HH - 1 : 0) * 16 + c]);
            if (ox) S -= __half2float(CSh[(ox < 0 ? WW - 1 : 0) * 16 + c]);
            if (oy && ox) S += __half2float(SXH[c * HWP + (oy < 0 ? HH - 1 : 0) * WW + (ox < 0 ? WW - 1 : 0)]);
            SA[c * 9 + lane] = S;
        }

        // stats: lanes = 4 rows x 7 col-segments of 8
        bool act = (lane < 28);
        int lc = act ? lane : 0;
        int rs = lc / 7, seg = lc - rs * 7;
        const __half* chb = SXH + c * HWP + seg * 8;
        float4 xwa = h4tof4(*(const uint2*)(XWh + c * WW + seg * 8));
        float4 xwb = h4tof4(*(const uint2*)(XWh + c * WW + seg * 8 + 4));
        float4 s4 = make_float4(0.f, 0.f, 0.f, 0.f);
        float4 q4 = make_float4(0.f, 0.f, 0.f, 0.f);
#pragma unroll 2
        for (int i = 0; i < 14; i++) {
            int y = i * 4 + rs;
            float hx = __half2float(XHh[c * HH + y]);
            uint4 u = *(const uint4*)(chb + y * WW);
            float4 va = h4tof4(make_uint2(u.x, u.y));
            float4 vb = h4tof4(make_uint2(u.z, u.w));
            if (act) {
                float t0 = va.x * hx * xwa.x, t1 = va.y * hx * xwa.y;
                float t2 = va.z * hx * xwa.z, t3 = va.w * hx * xwa.w;
                float t4 = vb.x * hx * xwb.x, t5 = vb.y * hx * xwb.y;
                float t6 = vb.z * hx * xwb.z, t7 = vb.w * hx * xwb.w;
                s4.x += t0 + t4; s4.y += t1 + t5; s4.z += t2 + t6; s4.w += t3 + t7;
                q4.x += t0 * t0 + t4 * t4; q4.y += t1 * t1 + t5 * t5;
                q4.z += t2 * t2 + t6 * t6; q4.w += t3 * t3 + t7 * t7;
            }
        }
        float sum = (s4.x + s4.y) + (s4.z + s4.w);
        float sq  = (q4.x + q4.y) + (q4.z + q4.w);
        sum = wred(sum); sq = wred(sq);
        if (lane == 0) {
            const float invhw = 1.f / (float)HWP;
            float mu = sum * invhw;
            float var = sq * invhw - mu * mu;
            if (var < 0.f) var = 0.f;
            float inv = rsqrtf(var + EPSV);
            MU[c] = mu;
            SSv[c] = inv * GNWs[c];
        }
    }
    __syncthreads();

    // ---- 3bB: collapsed conv taps (half2-dup, 12-stride, tid<144) || M2 dots (warps 8-15) ----
    if (tid < 144) {
        int i = tid / 9, k = tid - i * 9;
        float s = 0.f;
#pragma unroll
        for (int o = 0; o < CGC; o++) s += A1v[o] * w3[o * 144 + tid];
        unsigned short hs = __half_as_ushort(__float2half_rn(s));
        WCu[i * 12 + k] = (unsigned int)hs * 0x10001u;
    }
    if (warp >= 8) {
        int o = (warp - 8) * 2 + (lane >> 4);
        int l16 = lane & 15;
        float m = 0.f;
#pragma unroll
        for (int j = l16; j < 144; j += 16) m += w3[o * 144 + j] * SA[j];
#pragma unroll
        for (int o2 = 8; o2; o2 >>= 1) m += __shfl_xor_sync(0xffffffffu, m, o2, 16);
        if (l16 == 0) M2[o] = B3s[o] + m * (1.f / (float)HWP);
    }
    __syncthreads();

    // ---- 3bC: a2 softmax + per-channel coefs (lanes 0-15); pack a2c into WCu[..+9] ----
    if (tid < 16) {
        float m2 = M2[tid];
        float mx = m2;
#pragma unroll
        for (int o = 8; o; o >>= 1) mx = fmaxf(mx, __shfl_xor_sync(0xffffu, mx, o, 16));
        float e = expf(m2 - mx);
        float ssum = e;
#pragma unroll
        for (int o = 8; o; o >>= 1) ssum += __shfl_xor_sync(0xffffu, ssum, o, 16);
        float a = e / ssum;
        float s = SSv[tid];
        float a2c = a * s;
        WCu[tid * 12 + 9] = f2h2u(a2c);
        float c2 = a * (GNBs[tid] - MU[tid] * s);
#pragma unroll
        for (int o = 8; o; o >>= 1) c2 += __shfl_xor_sync(0xffffu, c2, o, 16);
        if (tid == 0) CONSTS[1] = c2;
    }
    __syncthreads();

    // ---- Phase 5: 8px/lane HFMA2 conv, channel-split halves, xor-combine -> sigmoid -> out ----
    // unit = 16 lanes: lanes 0-7 channels 0-7, lanes 8-15 channels 8-15, same 8px x 2 rows.
    {
        const float wconst = CONSTS[0] + CONSTS[1];
        int blk = tid >> 4;
        int l16 = tid & 15;
        int h8 = l16 >> 3;
        int l8 = l16 & 7;
        int blkc = (blk < 28) ? blk : 27;
        int y0 = blkc * 2;
        bool act = (blk < 28) && (l8 < 7);
        int xq8 = (l8 < 7) ? l8 : 6;
        bool hasT = (blkc > 0), hasB = (blkc < 27);
        unsigned int h0a = 0u, h0b = 0u, h0c = 0u, h0d = 0u;
        unsigned int h1a = 0u, h1b = 0u, h1c = 0u, h1d = 0u;
#pragma unroll 2
        for (int ci = 0; ci < 8; ci++) {
            int c = h8 * 8 + ci;
            const uint4* wp = (const uint4*)(WCu + c * 12);
            uint4 w03 = wp[0];                 // taps 0..3 (half2-dup)
            uint4 w47 = wp[1];                 // taps 4..7
            uint2 w8a2 = *(const uint2*)(WCu + c * 12 + 8);
            unsigned int w8 = w8a2.x;          // tap 8
            unsigned int a2ch = w8a2.y;        // a2c half2-dup
            uint4 wv = *(const uint4*)(XWh + c * WW + xq8 * 8);
            unsigned int xh2u = *(const unsigned int*)(XHh + c * HH + y0);
            unsigned int cf0h = hmul2u(a2ch, __byte_perm(xh2u, xh2u, 0x1010));
            unsigned int cf1h = hmul2u(a2ch, __byte_perm(xh2u, xh2u, 0x3232));
            const __half* chb = SXH + c * HWP;
            const __half* rT = hasT ? chb + (y0 - 1) * WW : ZR;
            const __half* rB = hasB ? chb + (y0 + 2) * WW : ZR;
            uint4 u;
            unsigned int p0, p2, p4, p6, p8;
            GETROW8(rT);                       // row y0-1 (zero row at edge)
            HTAPS8(h0a, h0b, h0c, h0d, w03.x, w03.y, w03.z);
            GETROW8(chb + y0 * WW);            // row y0
            HTAPSV8(h0a, h0b, h0c, h0d, w03.w, cf0h, w47.y);
            HTAPS8(h1a, h1b, h1c, h1d, w03.x, w03.y, w03.z);
            GETROW8(chb + (y0 + 1) * WW);      // row y0+1
            HTAPS8(h0a, h0b, h0c, h0d, w47.z, w47.w, w8);
            HTAPSV8(h1a, h1b, h1c, h1d, w03.w, cf1h, w47.y);
            GETROW8(rB);                       // row y0+2 (zero row at edge)
            HTAPS8(h1a, h1b, h1c, h1d, w47.z, w47.w, w8);
        }
        // fold fp16 8-channel partials to fp32, combine channel halves via xor-shuffle
        float r0f[8], r1f[8];
        {
            float2 f;
            f = u2f2(h0a); r0f[0] = f.x; r0f[1] = f.y;
            f = u2f2(h0b); r0f[2] = f.x; r0f[3] = f.y;
            f = u2f2(h0c); r0f[4] = f.x; r0f[5] = f.y;
            f = u2f2(h0d); r0f[6] = f.x; r0f[7] = f.y;
            f = u2f2(h1a); r1f[0] = f.x; r1f[1] = f.y;
            f = u2f2(h1b); r1f[2] = f.x; r1f[3] = f.y;
            f = u2f2(h1c); r1f[4] = f.x; r1f[5] = f.y;
            f = u2f2(h1d); r1f[6] = f.x; r1f[7] = f.y;
        }
#pragma unroll
        for (int j = 0; j < 8; j++) {
            r0f[j] += __shfl_xor_sync(0xffffffffu, r0f[j], 8, 16);
            r1f[j] += __shfl_xor_sync(0xffffffffu, r1f[j], 8, 16);
        }
        if (act) {
            // lane half 0 -> row y0, half 1 -> row y0+1
            int yr = y0 + h8;
            float s0 = sigm((h8 ? r1f[0] : r0f[0]) + wconst);
            float s1 = sigm((h8 ? r1f[1] : r0f[1]) + wconst);
            float s2 = sigm((h8 ? r1f[2] : r0f[2]) + wconst);
            float s3 = sigm((h8 ? r1f[3] : r0f[3]) + wconst);
            float s4 = sigm((h8 ? r1f[4] : r0f[4]) + wconst);
            float s5 = sigm((h8 ? r1f[5] : r0f[5]) + wconst);
            float s6 = sigm((h8 ? r1f[6] : r0f[6]) + wconst);
            float s7 = sigm((h8 ? r1f[7] : r0f[7]) + wconst);
            const __half* sb0 = SXH + yr * WW + xq8 * 8;
            float* ob0 = og + yr * WW + xq8 * 8;
#pragma unroll 4
            for (int c = 0; c < CGC; c++) {
                uint4 v = *(const uint4*)(sb0 + c * HWP);
                float4 a = h4tof4(make_uint2(v.x, v.y));
                float4 b = h4tof4(make_uint2(v.z, v.w));
                float4 o0, o1;
                o0.x = a.x * s0; o0.y = a.y * s1; o0.z = a.z * s2; o0.w = a.w * s3;
                o1.x = b.x * s4; o1.y = b.y * s5; o1.z = b.z * s6; o1.w = b.w * s7;
                __stcs((float4*)(ob0 + c * HWP), o0);
                __stcs((float4*)(ob0 + c * HWP + 4), o1);
            }
        }
    }
}

extern "C" void kernel_launch(void* const* d_in, const int* in_sizes, int n_in,
                              void* d_out, int out_size) {
    const float* x   = (const float*)d_in[0];
    const float* w1  = (const float*)d_in[1];
    const float* b1  = (const float*)d_in[2];
    const float* w3  = (const float*)d_in[3];
    const float* b3  = (const float*)d_in[4];
    const float* gnw = (const float*)d_in[5];
    const float* gnb = (const float*)d_in[6];
    float* out = (float*)d_out;

    cudaFuncSetAttribute(ema_fused_kernel,
                         cudaFuncAttributeMaxDynamicSharedMemorySize, SMEM_BYTES);
    ema_fused_kernel<<<NGRP, NT, SMEM_BYTES>>>(x, w1, b1, w3, b3, gnw, gnb, out);
}

// round 17
// speedup vs baseline: 1.0719x; 1.0719x over previous
#include <cuda_runtime.h>
#include <cuda_fp16.h>
#include <cstdint>

#define HH 56
#define WW 56
#define HWP 3136
#define CGC 16
#define NGRP 1024
#define NT 512
#define EPSV 1e-5f

// byte offsets into dynamic smem
#define OB_SX    0        // fp16 tile 16*3136
#define OB_XH    100352
#define OB_XW    102144
#define OB_RS    103936   // fp16, layout [h*16+c]
#define OB_CS    105728   // fp16, layout [x*16+c]
#define OB_W1    107520   // fp16 256 (half2 pair layout)
#define OB_WC    108544   // half2-dup conv taps + a2c, 16*12 uints
#define OB_SA    109312   // fp32 144
#define OB_B1    109888
#define OB_B3    109952
#define OB_GNW   110016
#define OB_GNB   110080
#define OB_MU    110144
#define OB_SS    110208
#define OB_M2    110272
#define OB_A1    110336
#define OB_A2C   110400
#define OB_CONST 110464
#define OB_ZR    110528   // 128B zero row
#define SMEM_BYTES 110656

__device__ __forceinline__ float wred(float v) {
#pragma unroll
    for (int o = 16; o; o >>= 1) v += __shfl_down_sync(0xffffffffu, v, o);
    return v;
}
__device__ __forceinline__ float sigm(float z) {
    return __fdividef(1.f, 1.f + __expf(-z));
}

__device__ __forceinline__ float4 h4tof4(uint2 u) {
    __half2 a = *reinterpret_cast<__half2*>(&u.x);
    __half2 b = *reinterpret_cast<__half2*>(&u.y);
    float2 fa = __half22float2(a), fb = __half22float2(b);
    return make_float4(fa.x, fa.y, fb.x, fb.y);
}
__device__ __forceinline__ unsigned int hfma2u(unsigned int a, unsigned int b, unsigned int c) {
    __half2 r = __hfma2(*reinterpret_cast<__half2*>(&a),
                        *reinterpret_cast<__half2*>(&b),
                        *reinterpret_cast<__half2*>(&c));
    return *reinterpret_cast<unsigned int*>(&r);
}
__device__ __forceinline__ unsigned int hmul2u(unsigned int a, unsigned int b) {
    __half2 r = __hmul2(*reinterpret_cast<__half2*>(&a),
                        *reinterpret_cast<__half2*>(&b));
    return *reinterpret_cast<unsigned int*>(&r);
}
__device__ __forceinline__ float2 u2f2(unsigned int a) {
    return __half22float2(*reinterpret_cast<__half2*>(&a));
}
__device__ __forceinline__ unsigned int f2h2u(float v) {
    __half2 h = __float2half2_rn(v);
    return *reinterpret_cast<unsigned int*>(&h);
}

// load one conv row (4px + halo) as raw half2 pairs, shifted pairs via PRMT
#define GETROWH(rowptr) do { \
    uint2 _u = *(const uint2*)((rowptr) + xqe * 4); \
    unsigned int _pu = __shfl_up_sync(0xffffffffu, _u.y, 1, 16); \
    unsigned int _nu = __shfl_down_sync(0xffffffffu, _u.x, 1, 16); \
    if (l16 == 0) _pu = 0u; \
    if (l16 == 13) _nu = 0u; \
    q01 = _u.x; q23 = _u.y; \
    p0 = __byte_perm(_pu, _u.x, 0x5432); \
    p2 = __byte_perm(_u.x, _u.y, 0x5432); \
    p4 = __byte_perm(_u.y, _nu, 0x5432); \
} while (0)

#define HTAPS(ha, hb, t0, t1, t2) do { \
    ha = hfma2u(t0, p0, hfma2u(t1, q01, hfma2u(t2, p2, ha))); \
    hb = hfma2u(t0, p2, hfma2u(t1, q23, hfma2u(t2, p4, hb))); \
} while (0)

#define HTAPSV(ha, hb, t0, tva, tvb, t2) do { \
    ha = hfma2u(t0, p0, hfma2u(tva, q01, hfma2u(t2, p2, ha))); \
    hb = hfma2u(t0, p2, hfma2u(tvb, q23, hfma2u(t2, p4, hb))); \
} while (0)

__global__ __launch_bounds__(NT, 2)
void ema_fused_kernel(const float* __restrict__ x,
                      const float* __restrict__ w1, const float* __restrict__ b1,
                      const float* __restrict__ w3, const float* __restrict__ b3,
                      const float* __restrict__ gnw, const float* __restrict__ gnb,
                      float* __restrict__ out) {
    extern __shared__ char smc[];
    __half* SXH = (__half*)(smc + OB_SX);
    __half* XHh = (__half*)(smc + OB_XH);
    __half* XWh = (__half*)(smc + OB_XW);
    __half* RSh = (__half*)(smc + OB_RS);
    __half* CSh = (__half*)(smc + OB_CS);
    __half* W1h = (__half*)(smc + OB_W1);
    unsigned int* WCu = (unsigned int*)(smc + OB_WC);
    float* SA  = (float*)(smc + OB_SA);
    float* B1s = (float*)(smc + OB_B1);
    float* B3s = (float*)(smc + OB_B3);
    float* GNWs = (float*)(smc + OB_GNW);
    float* GNBs = (float*)(smc + OB_GNB);
    float* MU  = (float*)(smc + OB_MU);
    float* SSv = (float*)(smc + OB_SS);
    float* M2  = (float*)(smc + OB_M2);
    float* A1v = (float*)(smc + OB_A1);
    float* CONSTS = (float*)(smc + OB_CONST);
    __half* ZR = (__half*)(smc + OB_ZR);

    const int tid = threadIdx.x;
    const int g = blockIdx.x;
    const float* gx = x + (size_t)g * (CGC * HWP);
    float* og = out + (size_t)g * (CGC * HWP);

    const int warp = tid >> 5;
    const int lane = tid & 31;

    // ---- Phase 0: streaming load tile (fp32 -> fp16, 8 px chunks) + params + zero row ----
    {
        const float4* gx4 = (const float4*)gx;
#pragma unroll 2
        for (int i = tid; i < (CGC * HWP) / 8; i += NT) {
            float4 v0 = __ldcs(gx4 + 2 * i);
            float4 v1 = __ldcs(gx4 + 2 * i + 1);
            __half2 h0 = __floats2half2_rn(v0.x, v0.y);
            __half2 h1 = __floats2half2_rn(v0.z, v0.w);
            __half2 h2 = __floats2half2_rn(v1.x, v1.y);
            __half2 h3 = __floats2half2_rn(v1.z, v1.w);
            uint4 u;
            u.x = *(unsigned int*)&h0; u.y = *(unsigned int*)&h1;
            u.z = *(unsigned int*)&h2; u.w = *(unsigned int*)&h3;
            *(uint4*)(SXH + i * 8) = u;
        }
        if (tid < 256) W1h[tid] = __float2half_rn(w1[tid]);
        if (tid < 16) {
            B1s[tid] = b1[tid]; B3s[tid] = b3[tid];
            GNWs[tid] = gnw[tid]; GNBs[tid] = gnb[tid];
        }
        if (tid >= 256 && tid < 288) ((float*)ZR)[tid - 256] = 0.f;
    }
    __syncthreads();

    // ---- Phase 1 (rebalanced): cols on 224 threads (4-px segs), rows on 256 threads ----
    // RS/CS stored transposed: RSh[h*16+c], CSh[x*16+c]
    if (tid < 224) {
        int c = tid / 14, seg = tid - c * 14;
        const __half* base = SXH + c * HWP + seg * 4;
        float4 sa = make_float4(0.f, 0.f, 0.f, 0.f);
#pragma unroll 8
        for (int y = 0; y < HH; y++) {
            float4 a = h4tof4(*(const uint2*)(base + y * WW));
            sa.x += a.x; sa.y += a.y; sa.z += a.z; sa.w += a.w;
        }
        CSh[(seg * 4 + 0) * 16 + c] = __float2half_rn(sa.x);
        CSh[(seg * 4 + 1) * 16 + c] = __float2half_rn(sa.y);
        CSh[(seg * 4 + 2) * 16 + c] = __float2half_rn(sa.z);
        CSh[(seg * 4 + 3) * 16 + c] = __float2half_rn(sa.w);
    } else if (tid < 480) {
        for (int r = tid - 224; r < CGC * HH; r += 256) {
            int c = r / HH, h = r - c * HH;
            const uint4* row = (const uint4*)(SXH + r * WW);
            float s = 0.f;
#pragma unroll
            for (int j = 0; j < 7; j++) {
                uint4 u = row[j];
                float4 a = h4tof4(make_uint2(u.x, u.y));
                float4 b = h4tof4(make_uint2(u.z, u.w));
                s += (a.x + a.y) + (a.z + a.w) + (b.x + b.y) + (b.z + b.w);
            }
            RSh[h * 16 + c] = __float2half_rn(s);
        }
    } else if (tid < 496) {
        // a1 = softmax(gn_b) (params only)
        int t = tid - 480;
        float gb = GNBs[t];
        float mx = gb;
#pragma unroll
        for (int o = 8; o; o >>= 1) mx = fmaxf(mx, __shfl_xor_sync(0xffffu, mx, o, 16));
        float e = expf(gb - mx);
        float ssum = e;
#pragma unroll
        for (int o = 8; o; o >>= 1) ssum += __shfl_xor_sync(0xffffu, ssum, o, 16);
        float a = e / ssum;
        A1v[t] = a;
        float cA = a * B3s[t];
#pragma unroll
        for (int o = 8; o; o >>= 1) cA += __shfl_xor_sync(0xffffu, cA, o, 16);
        if (t == 0) CONSTS[0] = cA;
    }
    __syncthreads();

    // ==== Merged Phase 2 (HFMA2 conv1x1+sigmoid) + SA + Phase 3 (stats), warp-per-channel ====
    {
        const int c = warp;
        const float inv56 = 1.f / 56.f;
        const uint4* w1p = (const uint4*)(W1h + c * CGC);
        uint4 wra = w1p[0], wrb = w1p[1];
        for (int ii = lane; ii < HH + WW; ii += 32) {
            const __half* base = (ii < HH) ? (RSh + ii * 16) : (CSh + (ii - HH) * 16);
            uint4 ua = *(const uint4*)base;
            uint4 ub = *(const uint4*)(base + 8);
            unsigned int h = 0u;
            h = hfma2u(wra.x, ua.x, h);
            h = hfma2u(wra.y, ua.y, h);
            h = hfma2u(wra.z, ua.z, h);
            h = hfma2u(wra.w, ua.w, h);
            h = hfma2u(wrb.x, ub.x, h);
            h = hfma2u(wrb.y, ub.y, h);
            h = hfma2u(wrb.z, ub.z, h);
            h = hfma2u(wrb.w, ub.w, h);
            float2 f = u2f2(h);
            float sg = sigm(B1s[c] + (f.x + f.y) * inv56);
            if (ii < HH) XHh[c * HH + ii] = __float2half_rn(sg);
            else         XWh[c * WW + (ii - HH)] = __float2half_rn(sg);
        }
        __syncwarp();

        // channel total + shifted sums SA (lanes 0-8), all channel-local
        float v = __half2float(RSh[lane * 16 + c]) +
                  ((lane < 24) ? __half2float(RSh[(lane + 32) * 16 + c]) : 0.f);
        v = wred(v);
        float vtot = __shfl_sync(0xffffffffu, v, 0);
        if (lane < 9) {
            int oy = lane / 3 - 1, ox = lane % 3 - 1;
            float S = vtot;
            if (oy) S -= __half2float(RSh[(oy < 0 ? HH - 1 : 0) * 16 + c]);
            if (ox) S -= __half2float(CSh[(ox < 0 ? WW - 1 : 0) * 16 + c]);
            if (oy && ox) S += __half2float(SXH[c * HWP + (oy < 0 ? HH - 1 : 0) * WW + (ox < 0 ? WW - 1 : 0)]);
            SA[c * 9 + lane] = S;
        }

        // stats: lanes = 4 rows x 7 col-segments of 8
        bool act = (lane < 28);
        int lc = act ? lane : 0;
        int rs = lc / 7, seg = lc - rs * 7;
        const __half* chb = SXH + c * HWP + seg * 8;
        float4 xwa = h4tof4(*(const uint2*)(XWh + c * WW + seg * 8));
        float4 xwb = h4tof4(*(const uint2*)(XWh + c * WW + seg * 8 + 4));
        float4 s4 = make_float4(0.f, 0.f, 0.f, 0.f);
        float4 q4 = make_float4(0.f, 0.f, 0.f, 0.f);
#pragma unroll 2
        for (int i = 0; i < 14; i++) {
            int y = i * 4 + rs;
            float hx = __half2float(XHh[c * HH + y]);
            uint4 u = *(const uint4*)(chb + y * WW);
            float4 va = h4tof4(make_uint2(u.x, u.y));
            float4 vb = h4tof4(make_uint2(u.z, u.w));
            if (act) {
                float t0 = va.x * hx * xwa.x, t1 = va.y * hx * xwa.y;
                float t2 = va.z * hx * xwa.z, t3 = va.w * hx * xwa.w;
                float t4 = vb.x * hx * xwb.x, t5 = vb.y * hx * xwb.y;
                float t6 = vb.z * hx * xwb.z, t7 = vb.w * hx * xwb.w;
                s4.x += t0 + t4; s4.y += t1 + t5; s4.z += t2 + t6; s4.w += t3 + t7;
                q4.x += t0 * t0 + t4 * t4; q4.y += t1 * t1 + t5 * t5;
                q4.z += t2 * t2 + t6 * t6; q4.w += t3 * t3 + t7 * t7;
            }
        }
        float sum = (s4.x + s4.y) + (s4.z + s4.w);
        float sq  = (q4.x + q4.y) + (q4.z + q4.w);
        sum = wred(sum); sq = wred(sq);
        if (lane == 0) {
            const float invhw = 1.f / (float)HWP;
            float mu = sum * invhw;
            float var = sq * invhw - mu * mu;
            if (var < 0.f) var = 0.f;
            float inv = rsqrtf(var + EPSV);
            MU[c] = mu;
            SSv[c] = inv * GNWs[c];
        }
    }
    __syncthreads();

    // ---- 3bB: collapsed conv taps (half2-dup, 12-stride, tid<144) || M2 dots (warps 8-15) ----
    if (tid < 144) {
        int i = tid / 9, k = tid - i * 9;
        float s = 0.f;
#pragma unroll
        for (int o = 0; o < CGC; o++) s += A1v[o] * w3[o * 144 + tid];
        unsigned short hs = __half_as_ushort(__float2half_rn(s));
        WCu[i * 12 + k] = (unsigned int)hs * 0x10001u;
    }
    if (warp >= 8) {
        int o = (warp - 8) * 2 + (lane >> 4);
        int l16 = lane & 15;
        float m = 0.f;
#pragma unroll
        for (int j = l16; j < 144; j += 16) m += w3[o * 144 + j] * SA[j];
#pragma unroll
        for (int o2 = 8; o2; o2 >>= 1) m += __shfl_xor_sync(0xffffffffu, m, o2, 16);
        if (l16 == 0) M2[o] = B3s[o] + m * (1.f / (float)HWP);
    }
    __syncthreads();

    // ---- 3bC: a2 softmax + per-channel coefs (lanes 0-15); pack a2c into WCu[..+9] ----
    if (tid < 16) {
        float m2 = M2[tid];
        float mx = m2;
#pragma unroll
        for (int o = 8; o; o >>= 1) mx = fmaxf(mx, __shfl_xor_sync(0xffffu, mx, o, 16));
        float e = expf(m2 - mx);
        float ssum = e;
#pragma unroll
        for (int o = 8; o; o >>= 1) ssum += __shfl_xor_sync(0xffffu, ssum, o, 16);
        float a = e / ssum;
        float s = SSv[tid];
        float a2c = a * s;
        WCu[tid * 12 + 9] = f2h2u(a2c);
        float c2 = a * (GNBs[tid] - MU[tid] * s);
#pragma unroll
        for (int o = 8; o; o >>= 1) c2 += __shfl_xor_sync(0xffffu, c2, o, 16);
        if (tid == 0) CONSTS[1] = c2;
    }
    __syncthreads();

    // ---- Phase 5: HFMA2 conv (fp16 partials, fold every 2 channels, FULL unroll) ----
    {
        const float wconst = CONSTS[0] + CONSTS[1];
        int blk = tid >> 4;
        int l16 = tid & 15;
        int blkc = (blk < 28) ? blk : 27;
        int y0 = blkc * 2;
        bool act = (blk < 28) && (l16 < 14);
        int xqe = (l16 < 14) ? l16 : 13;
        bool hasT = (blkc > 0), hasB = (blkc < 27);
        float4 acc0 = make_float4(wconst, wconst, wconst, wconst);
        float4 acc1 = acc0;
#pragma unroll
        for (int cb = 0; cb < CGC; cb += 2) {
            unsigned int h0a = 0u, h0b = 0u, h1a = 0u, h1b = 0u;
#pragma unroll
            for (int cc = 0; cc < 2; cc++) {
                int c = cb + cc;
                const uint4* wp = (const uint4*)(WCu + c * 12);
                uint4 w03 = wp[0];                 // taps 0..3 (half2-dup)
                uint4 w47 = wp[1];                 // taps 4..7
                uint2 w8a2 = *(const uint2*)(WCu + c * 12 + 8);
                unsigned int w8 = w8a2.x;          // tap 8
                unsigned int a2ch = w8a2.y;        // a2c half2-dup
                uint2 wvu = *(const uint2*)(XWh + c * WW + xqe * 4);  // raw half2 pair
                unsigned int xh2u = *(const unsigned int*)(XHh + c * HH + y0);
                unsigned int cf0h = hmul2u(a2ch, __byte_perm(xh2u, xh2u, 0x1010));
                unsigned int cf1h = hmul2u(a2ch, __byte_perm(xh2u, xh2u, 0x3232));
                unsigned int tv0a = hfma2u(cf0h, wvu.x, w47.x);  // attn folded into center tap
                unsigned int tv0b = hfma2u(cf0h, wvu.y, w47.x);
                unsigned int tv1a = hfma2u(cf1h, wvu.x, w47.x);
                unsigned int tv1b = hfma2u(cf1h, wvu.y, w47.x);
                const __half* chb = SXH + c * HWP;
                const __half* rT = hasT ? chb + (y0 - 1) * WW : ZR;
                const __half* rB = hasB ? chb + (y0 + 2) * WW : ZR;
                unsigned int q01, q23, p0, p2, p4;
                GETROWH(rT);                       // row y0-1 (zero row at edge)
                HTAPS(h0a, h0b, w03.x, w03.y, w03.z);
                GETROWH(chb + y0 * WW);            // row y0
                HTAPSV(h0a, h0b, w03.w, tv0a, tv0b, w47.y);
                HTAPS(h1a, h1b, w03.x, w03.y, w03.z);
                GETROWH(chb + (y0 + 1) * WW);      // row y0+1
                HTAPS(h0a, h0b, w47.z, w47.w, w8);
                HTAPSV(h1a, h1b, w03.w, tv1a, tv1b, w47.y);
                GETROWH(rB);                       // row y0+2 (zero row at edge)
                HTAPS(h1a, h1b, w47.z, w47.w, w8);
            }
            // fold fp16 2-channel partials into fp32 accumulators
            float2 f;
            f = u2f2(h0a); acc0.x += f.x; acc0.y += f.y;
            f = u2f2(h0b); acc0.z += f.x; acc0.w += f.y;
            f = u2f2(h1a); acc1.x += f.x; acc1.y += f.y;
            f = u2f2(h1b); acc1.z += f.x; acc1.w += f.y;
        }
        if (act) {
            float4 s0, s1;
            s0.x = sigm(acc0.x); s0.y = sigm(acc0.y); s0.z = sigm(acc0.z); s0.w = sigm(acc0.w);
            s1.x = sigm(acc1.x); s1.y = sigm(acc1.y); s1.z = sigm(acc1.z); s1.w = sigm(acc1.w);
#pragma unroll 4
            for (int c = 0; c < CGC; c++) {
                const __half* sb = SXH + c * HWP + y0 * WW + xqe * 4;
                float* ob = og + c * HWP + y0 * WW + xqe * 4;
                float4 v0 = h4tof4(*(const uint2*)sb);
                float4 v1 = h4tof4(*(const uint2*)(sb + WW));
                float4 o0, o1;
                o0.x = v0.x * s0.x; o0.y = v0.y * s0.y; o0.z = v0.z * s0.z; o0.w = v0.w * s0.w;
                o1.x = v1.x * s1.x; o1.y = v1.y * s1.y; o1.z = v1.z * s1.z; o1.w = v1.w * s1.w;
                __stcs((float4*)ob, o0);
                __stcs((float4*)(ob + WW), o1);
            }
        }
    }
}

extern "C" void kernel_launch(void* const* d_in, const int* in_sizes, int n_in,
                              void* d_out, int out_size) {
    const float* x   = (const float*)d_in[0];
    const float* w1  = (const float*)d_in[1];
    const float* b1  = (const float*)d_in[2];
    const float* w3  = (const float*)d_in[3];
    const float* b3  = (const float*)d_in[4];
    const float* gnw = (const float*)d_in[5];
    const float* gnb = (const float*)d_in[6];
    float* out = (float*)d_out;

    cudaFuncSetAttribute(ema_fused_kernel,
                         cudaFuncAttributeMaxDynamicSharedMemorySize, SMEM_BYTES);
    ema_fused_kernel<<<NGRP, NT, SMEM_BYTES>>>(x, w1, b1, w3, b3, gnw, gnb, out);
}